// round 3
// baseline (speedup 1.0000x reference)
#include <cuda_runtime.h>
#include <cstdint>

#define B        2
#define N_PRE    50000
#define N_POST   50000
#define N_SYN    10000000
#define N_TYPES  20
#define N_BASIS  5

#define MASK_WORDS ((N_PRE + 15) / 16)   // 2 bits/neuron -> 3125 words (12.5 KB)

__device__ uint32_t g_spike_mask[MASK_WORDS];

// Fused: zero the poisoned output (float4) + build the packed spike mask.
__global__ void prep_kernel(const float* __restrict__ spikes,
                            float* __restrict__ out, int out_n)
{
    int tid = blockIdx.x * blockDim.x + threadIdx.x;
    int nthreads = gridDim.x * blockDim.x;

    // Zero via float4 (out_n = 500000, divisible by 4; guard anyway).
    int n4 = out_n >> 2;
    float4* out4 = (float4*)out;
    for (int i = tid; i < n4; i += nthreads)
        out4[i] = make_float4(0.f, 0.f, 0.f, 0.f);
    for (int i = (n4 << 2) + tid; i < out_n; i += nthreads)
        out[i] = 0.0f;

    // Build mask: word w covers neurons [16w, 16w+16).
    for (int w = tid; w < MASK_WORDS; w += nthreads) {
        uint32_t m = 0;
        int base = w * 16;
        #pragma unroll
        for (int j = 0; j < 16; j++) {
            int pre = base + j;
            if (pre < N_PRE) {
                uint32_t b0 = (spikes[pre] != 0.0f) ? 1u : 0u;
                uint32_t b1 = (spikes[N_PRE + pre] != 0.0f) ? 1u : 0u;
                m |= (b0 | (b1 << 1)) << (j * 2);
            }
        }
        g_spike_mask[w] = m;
    }
}

// Process one int4 = two synapses, given their 2-bit fire masks.
__device__ __forceinline__ void process_pair(
    int4 v, int s, uint32_t ba, uint32_t bb,
    const float* __restrict__ weights, const int* __restrict__ syn_ids,
    const float* __restrict__ sb, float* __restrict__ out)
{
    if ((ba | bb) == 0u) return;   // ~92% of pairs

    float2 wv = __ldg((const float2*)(weights + s));
    int2   tt = __ldg((const int2*)(syn_ids + s));

    if (ba) {
        const float* bt = sb + tt.x * N_BASIS;
        float c0 = wv.x * bt[0], c1 = wv.x * bt[1], c2 = wv.x * bt[2],
              c3 = wv.x * bt[3], c4 = wv.x * bt[4];
        if (ba & 1u) {
            float* o = out + (size_t)v.x * N_BASIS;
            atomicAdd(o + 0, c0); atomicAdd(o + 1, c1); atomicAdd(o + 2, c2);
            atomicAdd(o + 3, c3); atomicAdd(o + 4, c4);
        }
        if (ba & 2u) {
            float* o = out + ((size_t)N_POST + v.x) * N_BASIS;
            atomicAdd(o + 0, c0); atomicAdd(o + 1, c1); atomicAdd(o + 2, c2);
            atomicAdd(o + 3, c3); atomicAdd(o + 4, c4);
        }
    }
    if (bb) {
        const float* bt = sb + tt.y * N_BASIS;
        float c0 = wv.y * bt[0], c1 = wv.y * bt[1], c2 = wv.y * bt[2],
              c3 = wv.y * bt[3], c4 = wv.y * bt[4];
        if (bb & 1u) {
            float* o = out + (size_t)v.z * N_BASIS;
            atomicAdd(o + 0, c0); atomicAdd(o + 1, c1); atomicAdd(o + 2, c2);
            atomicAdd(o + 3, c3); atomicAdd(o + 4, c4);
        }
        if (bb & 2u) {
            float* o = out + ((size_t)N_POST + v.z) * N_BASIS;
            atomicAdd(o + 0, c0); atomicAdd(o + 1, c1); atomicAdd(o + 2, c2);
            atomicAdd(o + 3, c3); atomicAdd(o + 4, c4);
        }
    }
}

__global__ __launch_bounds__(256)
void accum_kernel(const float* __restrict__ weights,       // [N_SYN]
                  const float* __restrict__ basis,         // [N_TYPES, N_BASIS]
                  const int4*  __restrict__ syn_idx4,      // [N_SYN/2]
                  const int*   __restrict__ syn_ids,       // [N_SYN]
                  float*       __restrict__ out)           // [B*N_POST, N_BASIS]
{
    __shared__ uint32_t smask[MASK_WORDS];
    __shared__ float sb[N_TYPES * N_BASIS];

    for (int i = threadIdx.x; i < MASK_WORDS; i += blockDim.x)
        smask[i] = g_spike_mask[i];
    if (threadIdx.x < N_TYPES * N_BASIS) sb[threadIdx.x] = basis[threadIdx.x];
    __syncthreads();

    const int NV = N_SYN / 2;
    const int stride = gridDim.x * blockDim.x;
    int i = blockIdx.x * blockDim.x + threadIdx.x;

    // Unrolled x4: front-batch the index loads (MLP=4), then mask lookups,
    // then the (rare) heavy path.
    for (; i + 3 * stride < NV; i += 4 * stride) {
        int4 v0 = syn_idx4[i];
        int4 v1 = syn_idx4[i + stride];
        int4 v2 = syn_idx4[i + 2 * stride];
        int4 v3 = syn_idx4[i + 3 * stride];

        uint32_t ba0 = (smask[v0.y >> 4] >> ((v0.y & 15) << 1)) & 3u;
        uint32_t bb0 = (smask[v0.w >> 4] >> ((v0.w & 15) << 1)) & 3u;
        uint32_t ba1 = (smask[v1.y >> 4] >> ((v1.y & 15) << 1)) & 3u;
        uint32_t bb1 = (smask[v1.w >> 4] >> ((v1.w & 15) << 1)) & 3u;
        uint32_t ba2 = (smask[v2.y >> 4] >> ((v2.y & 15) << 1)) & 3u;
        uint32_t bb2 = (smask[v2.w >> 4] >> ((v2.w & 15) << 1)) & 3u;
        uint32_t ba3 = (smask[v3.y >> 4] >> ((v3.y & 15) << 1)) & 3u;
        uint32_t bb3 = (smask[v3.w >> 4] >> ((v3.w & 15) << 1)) & 3u;

        process_pair(v0, (i) * 2,              ba0, bb0, weights, syn_ids, sb, out);
        process_pair(v1, (i + stride) * 2,     ba1, bb1, weights, syn_ids, sb, out);
        process_pair(v2, (i + 2 * stride) * 2, ba2, bb2, weights, syn_ids, sb, out);
        process_pair(v3, (i + 3 * stride) * 2, ba3, bb3, weights, syn_ids, sb, out);
    }
    for (; i < NV; i += stride) {
        int4 v = syn_idx4[i];
        uint32_t ba = (smask[v.y >> 4] >> ((v.y & 15) << 1)) & 3u;
        uint32_t bb = (smask[v.w >> 4] >> ((v.w & 15) << 1)) & 3u;
        process_pair(v, i * 2, ba, bb, weights, syn_ids, sb, out);
    }
}

extern "C" void kernel_launch(void* const* d_in, const int* in_sizes, int n_in,
                              void* d_out, int out_size)
{
    const float* spikes  = (const float*)d_in[0];   // rec_z_buf [B, N_PRE]
    const float* weights = (const float*)d_in[1];   // weight_values [N_SYN]
    const float* basis   = (const float*)d_in[2];   // synaptic_basis_weights [20,5]
    const int4*  syn_idx = (const int4*)d_in[3];    // synapse_indices [N_SYN,2]
    const int*   syn_ids = (const int*)d_in[4];     // syn_ids [N_SYN]
    float* out = (float*)d_out;                     // [B*N_POST, N_BASIS]

    prep_kernel<<<489, 256>>>(spikes, out, out_size);

    accum_kernel<<<1184, 256>>>(weights, basis, syn_idx, syn_ids, out);
}

// round 4
// speedup vs baseline: 1.2723x; 1.2723x over previous
#include <cuda_runtime.h>
#include <cstdint>

#define B        2
#define N_PRE    50000
#define N_POST   50000
#define N_SYN    10000000
#define N_TYPES  20
#define N_BASIS  5

#define MASK_WORDS ((N_PRE + 15) / 16)   // 2 bits/neuron -> 3125 words (12.5 KB)

__device__ uint32_t g_spike_mask[MASK_WORDS];

// Fused: zero the poisoned output (float4) + build the packed spike mask.
__global__ void prep_kernel(const float* __restrict__ spikes,
                            float* __restrict__ out, int out_n)
{
    int tid = blockIdx.x * blockDim.x + threadIdx.x;
    int nthreads = gridDim.x * blockDim.x;

    int n4 = out_n >> 2;
    float4* out4 = (float4*)out;
    for (int i = tid; i < n4; i += nthreads)
        out4[i] = make_float4(0.f, 0.f, 0.f, 0.f);
    for (int i = (n4 << 2) + tid; i < out_n; i += nthreads)
        out[i] = 0.0f;

    for (int w = tid; w < MASK_WORDS; w += nthreads) {
        uint32_t m = 0;
        int base = w * 16;
        #pragma unroll
        for (int j = 0; j < 16; j++) {
            int pre = base + j;
            if (pre < N_PRE) {
                uint32_t b0 = (spikes[pre] != 0.0f) ? 1u : 0u;
                uint32_t b1 = (spikes[N_PRE + pre] != 0.0f) ? 1u : 0u;
                m |= (b0 | (b1 << 1)) << (j * 2);
            }
        }
        g_spike_mask[w] = m;
    }
}

// Emit atomics for one firing synapse (2-bit batch mask m, weight w, type t).
__device__ __forceinline__ void emit(uint32_t m, int post, float w, int t,
                                     const float* __restrict__ sb,
                                     float* __restrict__ out)
{
    if (m == 0u) return;
    const float* bt = sb + t * N_BASIS;
    float c0 = w * bt[0], c1 = w * bt[1], c2 = w * bt[2],
          c3 = w * bt[3], c4 = w * bt[4];
    if (m & 1u) {
        float* o = out + (size_t)post * N_BASIS;
        atomicAdd(o + 0, c0); atomicAdd(o + 1, c1); atomicAdd(o + 2, c2);
        atomicAdd(o + 3, c3); atomicAdd(o + 4, c4);
    }
    if (m & 2u) {
        float* o = out + ((size_t)N_POST + post) * N_BASIS;
        atomicAdd(o + 0, c0); atomicAdd(o + 1, c1); atomicAdd(o + 2, c2);
        atomicAdd(o + 3, c3); atomicAdd(o + 4, c4);
    }
}

__global__ __launch_bounds__(256)
void accum_kernel(const float* __restrict__ weights,       // [N_SYN]
                  const float* __restrict__ basis,         // [N_TYPES, N_BASIS]
                  const int4*  __restrict__ syn_idx4,      // [N_SYN/2] (post,pre)x2
                  const int4*  __restrict__ syn_ids4,      // [N_SYN/4]
                  float*       __restrict__ out)           // [B*N_POST, N_BASIS]
{
    __shared__ uint32_t smask[MASK_WORDS];
    __shared__ float sb[N_TYPES * N_BASIS];

    for (int i = threadIdx.x; i < MASK_WORDS; i += blockDim.x)
        smask[i] = g_spike_mask[i];
    if (threadIdx.x < N_TYPES * N_BASIS) sb[threadIdx.x] = basis[threadIdx.x];
    __syncthreads();

    const int NG = N_SYN / 4;                 // 4 consecutive synapses per group
    const int stride = gridDim.x * blockDim.x;

    for (int g = blockIdx.x * blockDim.x + threadIdx.x; g < NG; g += stride) {
        // Two adjacent int4 loads: 32 contiguous bytes of the index stream.
        int4 u = syn_idx4[g * 2];             // syn 4g+0: (u.x,u.y)  4g+1: (u.z,u.w)
        int4 v = syn_idx4[g * 2 + 1];         // syn 4g+2: (v.x,v.y)  4g+3: (v.z,v.w)

        uint32_t m0 = (smask[u.y >> 4] >> ((u.y & 15) << 1)) & 3u;
        uint32_t m1 = (smask[u.w >> 4] >> ((u.w & 15) << 1)) & 3u;
        uint32_t m2 = (smask[v.y >> 4] >> ((v.y & 15) << 1)) & 3u;
        uint32_t m3 = (smask[v.w >> 4] >> ((v.w & 15) << 1)) & 3u;

        if ((m0 | m1 | m2 | m3) == 0u) continue;   // ~85% of groups

        float4 wv = __ldg((const float4*)(weights + g * 4));
        int4   tt = __ldg(syn_ids4 + g);

        emit(m0, u.x, wv.x, tt.x, sb, out);
        emit(m1, u.z, wv.y, tt.y, sb, out);
        emit(m2, v.x, wv.z, tt.z, sb, out);
        emit(m3, v.z, wv.w, tt.w, sb, out);
    }
}

extern "C" void kernel_launch(void* const* d_in, const int* in_sizes, int n_in,
                              void* d_out, int out_size)
{
    const float* spikes  = (const float*)d_in[0];   // rec_z_buf [B, N_PRE]
    const float* weights = (const float*)d_in[1];   // weight_values [N_SYN]
    const float* basis   = (const float*)d_in[2];   // synaptic_basis_weights [20,5]
    const int4*  syn_idx = (const int4*)d_in[3];    // synapse_indices [N_SYN,2]
    const int4*  syn_ids = (const int4*)d_in[4];    // syn_ids [N_SYN]
    float* out = (float*)d_out;                     // [B*N_POST, N_BASIS]

    prep_kernel<<<489, 256>>>(spikes, out, out_size);

    accum_kernel<<<1184, 256>>>(weights, basis, syn_idx, syn_ids, out);
}

// round 5
// speedup vs baseline: 1.4265x; 1.1212x over previous
#include <cuda_runtime.h>
#include <cstdint>

#define B        2
#define N_PRE    50000
#define N_POST   50000
#define N_SYN    10000000
#define N_TYPES  20
#define N_BASIS  5

#define MASK_WORDS (N_PRE / 16)          // 3125 words exactly (2 bits/neuron)
#define ROW_PAD    8                     // padded scratch row: 8 floats (32B)
#define SCRATCH_N  (B * N_POST * ROW_PAD)

__device__ uint32_t g_spike_mask[MASK_WORDS];
__device__ __align__(32) float g_scratch[SCRATCH_N];   // 3.2 MB, L2-resident

// ---------------------------------------------------------------------------
// prep: zero scratch (float4) + build packed 2-bit spike mask (float4 reads)
__global__ void prep_kernel(const float* __restrict__ spikes)
{
    int tid = blockIdx.x * blockDim.x + threadIdx.x;
    int nthreads = gridDim.x * blockDim.x;

    float4* s4 = (float4*)g_scratch;
    const int NS4 = SCRATCH_N / 4;                    // 200000
    for (int i = tid; i < NS4; i += nthreads)
        s4[i] = make_float4(0.f, 0.f, 0.f, 0.f);

    const float4* sp0 = (const float4*)spikes;                 // batch 0
    const float4* sp1 = (const float4*)(spikes + N_PRE);       // batch 1
    for (int w = tid; w < MASK_WORDS; w += nthreads) {
        uint32_t m = 0;
        #pragma unroll
        for (int q = 0; q < 4; q++) {                // 4 float4 per batch = 16 neurons
            float4 a = sp0[w * 4 + q];
            float4 b = sp1[w * 4 + q];
            int j = q * 4;
            m |= ((a.x != 0.f) ? 1u : 0u) << (2 * (j + 0));
            m |= ((a.y != 0.f) ? 1u : 0u) << (2 * (j + 1));
            m |= ((a.z != 0.f) ? 1u : 0u) << (2 * (j + 2));
            m |= ((a.w != 0.f) ? 1u : 0u) << (2 * (j + 3));
            m |= ((b.x != 0.f) ? 2u : 0u) << (2 * (j + 0));
            m |= ((b.y != 0.f) ? 2u : 0u) << (2 * (j + 1));
            m |= ((b.z != 0.f) ? 2u : 0u) << (2 * (j + 2));
            m |= ((b.w != 0.f) ? 2u : 0u) << (2 * (j + 3));
        }
        g_spike_mask[w] = m;
    }
}

// ---------------------------------------------------------------------------
__device__ __forceinline__ void red4(float* p, float c0, float c1, float c2, float c3)
{
    asm volatile("red.global.add.v4.f32 [%0], {%1, %2, %3, %4};"
                 :: "l"(p), "f"(c0), "f"(c1), "f"(c2), "f"(c3) : "memory");
}

// One firing synapse: lazy gathers + 2 reduction ops per firing batch.
__device__ __forceinline__ void emit_syn(uint32_t m, int syn, int post,
                                         const float* __restrict__ weights,
                                         const int*   __restrict__ syn_ids,
                                         const float* __restrict__ sb)
{
    if (m == 0u) return;
    float w = __ldg(weights + syn);
    int   t = __ldg(syn_ids + syn);
    const float* bt = sb + t * N_BASIS;
    float c0 = w * bt[0], c1 = w * bt[1], c2 = w * bt[2],
          c3 = w * bt[3], c4 = w * bt[4];
    if (m & 1u) {
        float* o = g_scratch + (size_t)post * ROW_PAD;
        red4(o, c0, c1, c2, c3);
        atomicAdd(o + 4, c4);
    }
    if (m & 2u) {
        float* o = g_scratch + ((size_t)N_POST + post) * ROW_PAD;
        red4(o, c0, c1, c2, c3);
        atomicAdd(o + 4, c4);
    }
}

__global__ __launch_bounds__(256)
void accum_kernel(const float* __restrict__ weights,       // [N_SYN]
                  const float* __restrict__ basis,         // [N_TYPES, N_BASIS]
                  const int4*  __restrict__ syn_idx4,      // [N_SYN/2]
                  const int*   __restrict__ syn_ids)       // [N_SYN]
{
    __shared__ uint32_t smask[MASK_WORDS];
    __shared__ float sb[N_TYPES * N_BASIS];

    for (int i = threadIdx.x; i < MASK_WORDS; i += blockDim.x)
        smask[i] = g_spike_mask[i];
    if (threadIdx.x < N_TYPES * N_BASIS) sb[threadIdx.x] = basis[threadIdx.x];
    __syncthreads();

    const int NG = N_SYN / 4;                 // 4 consecutive synapses / thread
    const int stride = gridDim.x * blockDim.x;

    for (int g = blockIdx.x * blockDim.x + threadIdx.x; g < NG; g += stride) {
        // 32 contiguous bytes of the index stream, streaming (evict-first).
        int4 u = __ldcs(syn_idx4 + g * 2);     // syn 4g+0:(u.x,u.y) 4g+1:(u.z,u.w)
        int4 v = __ldcs(syn_idx4 + g * 2 + 1); // syn 4g+2:(v.x,v.y) 4g+3:(v.z,v.w)

        uint32_t m0 = (smask[u.y >> 4] >> ((u.y & 15) << 1)) & 3u;
        uint32_t m1 = (smask[u.w >> 4] >> ((u.w & 15) << 1)) & 3u;
        uint32_t m2 = (smask[v.y >> 4] >> ((v.y & 15) << 1)) & 3u;
        uint32_t m3 = (smask[v.w >> 4] >> ((v.w & 15) << 1)) & 3u;

        if ((m0 | m1 | m2 | m3) == 0u) continue;   // ~85% of groups

        int s = g * 4;
        emit_syn(m0, s + 0, u.x, weights, syn_ids, sb);
        emit_syn(m1, s + 1, u.z, weights, syn_ids, sb);
        emit_syn(m2, s + 2, v.x, weights, syn_ids, sb);
        emit_syn(m3, s + 3, v.z, weights, syn_ids, sb);
    }
}

// ---------------------------------------------------------------------------
// compact: out[row][0..4] = scratch[row][0..4]; fully overwrites out.
__global__ void compact_kernel(float* __restrict__ out, int out_n)
{
    int k = blockIdx.x * blockDim.x + threadIdx.x;   // float4 index into out
    int n4 = out_n >> 2;
    if (k < n4) {
        float4 r;
        int j0 = k * 4;
        r.x = g_scratch[((j0 + 0) / N_BASIS) * ROW_PAD + (j0 + 0) % N_BASIS];
        r.y = g_scratch[((j0 + 1) / N_BASIS) * ROW_PAD + (j0 + 1) % N_BASIS];
        r.z = g_scratch[((j0 + 2) / N_BASIS) * ROW_PAD + (j0 + 2) % N_BASIS];
        r.w = g_scratch[((j0 + 3) / N_BASIS) * ROW_PAD + (j0 + 3) % N_BASIS];
        ((float4*)out)[k] = r;
    }
    // tail (out_n % 4) — handle generically
    int tail_start = n4 * 4;
    int j = tail_start + k;
    if (k < out_n - tail_start)
        out[j] = g_scratch[(j / N_BASIS) * ROW_PAD + j % N_BASIS];
}

extern "C" void kernel_launch(void* const* d_in, const int* in_sizes, int n_in,
                              void* d_out, int out_size)
{
    const float* spikes  = (const float*)d_in[0];   // rec_z_buf [B, N_PRE]
    const float* weights = (const float*)d_in[1];   // weight_values [N_SYN]
    const float* basis   = (const float*)d_in[2];   // synaptic_basis_weights [20,5]
    const int4*  syn_idx = (const int4*)d_in[3];    // synapse_indices [N_SYN,2]
    const int*   syn_ids = (const int*)d_in[4];     // syn_ids [N_SYN]
    float* out = (float*)d_out;                     // [B*N_POST, N_BASIS]

    prep_kernel<<<1184, 256>>>(spikes);

    accum_kernel<<<1184, 256>>>(weights, basis, syn_idx, syn_ids);

    {
        int n4 = (out_size >> 2) + 4;               // covers vector body + tail
        compact_kernel<<<(n4 + 255) / 256, 256>>>(out, out_size);
    }
}